// round 17
// baseline (speedup 1.0000x reference)
#include <cuda_runtime.h>
#include <math.h>

#define N_NODES 100000
#define N_EDGES 600000
#define NF      128
#define NC      64
#define SCAN_T  1024
#define SCAN_B  ((N_NODES + SCAN_T - 1) / SCAN_T)   // 98 blocks <= 148 SMs (spin-safe)

// proj tiling: 8 warps x 16 rows = 128 node-rows per block
#define PROJ_ROWS   128
#define PROJ_BLOCKS ((N_NODES + PROJ_ROWS - 1) / PROJ_ROWS)
// dynamic smem layout (words): x_s 2 x 128*32, w_p uint2[16*8*32], g_s[128]
#define XS_WORDS      4096
#define WP_OFF_W      (2 * XS_WORDS)
#define GS_OFF_W      (WP_OFF_W + 16 * 8 * 32 * 2)
#define PROJ_SMEM_B   ((GS_OFF_W + NF) * 4)

#define PK_MASK   0x3FFFFFFFFFFULL
#define PK_ONE    (1ULL << 42)
#define PK_SCALE  1048576.0f
#define PK_INV    (1.0f / 1048576.0f)

// ---------------- scratch (static; zero at module load / reset per call) ----------------
__device__ float              g_z0[(size_t)N_NODES * NC];
__device__ float              g_z1[(size_t)N_NODES * NC];
__device__ unsigned long long g_packed[N_NODES];   // (cnt<<42)|fx(deg); reset by prop_a
__device__ float              g_dinv[N_NODES];
__device__ int                g_indptr[N_NODES + 1];
__device__ int                g_cursor[N_NODES];
__device__ int                g_blocksum[SCAN_B];
__device__ int                g_scan_done;          // reset by csr_fill
__device__ int2               g_edge[N_EDGES];

__device__ __forceinline__ unsigned int f2tf32(float v) {
    unsigned int r;
    asm("cvt.rna.tf32.f32 %0, %1;" : "=r"(r) : "f"(v));
    return r;
}

__device__ __forceinline__ void cp16(unsigned int smem, const void* g) {
    asm volatile("cp.async.ca.shared.global [%0], [%1], 16;" :: "r"(smem), "l"(g));
}
__device__ __forceinline__ void cp_commit() {
    asm volatile("cp.async.commit_group;");
}
template <int N>
__device__ __forceinline__ void cp_wait() {
    asm volatile("cp.async.wait_group %0;" :: "n"(N));
}

// ---------------- edge prep: single packed 64-bit atomic per edge ----------------
__global__ void k_edge_prep(const int* __restrict__ ei_col,
                            const float* __restrict__ ewt) {
    int e = blockIdx.x * blockDim.x + threadIdx.x;
    if (e >= N_EDGES) return;
    float w = ewt[e];
    float s = (fabsf(w) > 0.0f) ? (1.0f / (1.0f + __expf(-w))) : 0.0f;
    unsigned long long pk = PK_ONE |
        (unsigned long long)(unsigned int)(s * PK_SCALE + 0.5f);
    atomicAdd(&g_packed[ei_col[e]], pk);
}

// ---------------- fused scan: decode packed -> dinv, single-pass scan w/ spin ----------------
__global__ void __launch_bounds__(SCAN_T)
k_scan() {
    __shared__ int warp_sums[32];
    __shared__ int offset_s;
    int tid  = threadIdx.x;
    int lane = tid & 31;
    int wid  = tid >> 5;
    int i = blockIdx.x * SCAN_T + tid;

    unsigned long long p = (i < N_NODES) ? g_packed[i] : 0ULL;
    int v = (int)(p >> 42);
    if (i < N_NODES) {
        float deg = 1.0f + (float)(p & PK_MASK) * PK_INV;
        g_dinv[i] = rsqrtf(deg);
    }

    int s = v;
#pragma unroll
    for (int off = 1; off < 32; off <<= 1) {
        int t = __shfl_up_sync(0xffffffffu, s, off);
        if (lane >= off) s += t;
    }
    if (lane == 31) warp_sums[wid] = s;
    __syncthreads();
    if (wid == 0) {
        int ws = warp_sums[lane];
#pragma unroll
        for (int off = 1; off < 32; off <<= 1) {
            int t = __shfl_up_sync(0xffffffffu, ws, off);
            if (lane >= off) ws += t;
        }
        warp_sums[lane] = ws;
    }
    __syncthreads();
    int warp_prefix = (wid > 0) ? warp_sums[wid - 1] : 0;
    int excl = s + warp_prefix - v;

    if (tid == SCAN_T - 1) {
        g_blocksum[blockIdx.x] = s + warp_prefix;
        __threadfence();
        atomicAdd(&g_scan_done, 1);
    }
    if (tid == 0) {
        while (((volatile int*)&g_scan_done)[0] < SCAN_B) { }
    }
    __syncthreads();

    if (tid < 32) {
        int acc = 0;
        for (int b = tid; b < blockIdx.x; b += 32)
            acc += ((volatile int*)g_blocksum)[b];
#pragma unroll
        for (int off = 16; off >= 1; off >>= 1)
            acc += __shfl_xor_sync(0xffffffffu, acc, off);
        if (tid == 0) offset_s = acc;
    }
    __syncthreads();

    if (i < N_NODES) {
        int pos = excl + offset_s;
        g_indptr[i] = pos;
        g_cursor[i] = pos;
        if (i == 0) g_indptr[N_NODES] = N_EDGES;
    }
}

__global__ void k_csr_fill(const int* __restrict__ ei_row,
                           const int* __restrict__ ei_col,
                           const float* __restrict__ ewt) {
    int e = blockIdx.x * blockDim.x + threadIdx.x;
    if (e == 0) g_scan_done = 0;
    if (e >= N_EDGES) return;
    int row = ei_row[e];
    int col = ei_col[e];
    float w = ewt[e];
    float s = (fabsf(w) > 0.0f) ? (1.0f / (1.0f + __expf(-w))) : 0.0f;
    float nrm = g_dinv[row] * s * g_dinv[col];
    int pos = atomicAdd(&g_cursor[col], 1);
    g_edge[pos] = make_int2(row, __float_as_int(nrm));
}

// ---------------- TF32 tensor-core projection, cp.async double-buffered ----------------
// x staged per 32-col chunk (16KB) with XOR swizzle (c4 ^ row&7): coalesced 128B
// fills AND conflict-free fragment LDS. A feeds raw fp32 bits (tf32 = top bits).
__device__ __forceinline__ void proj_load_chunk(
    unsigned int xs_smem, const float* __restrict__ x, int base, int kc, int tid) {
#pragma unroll
    for (int j = 0; j < 4; j++) {
        int idx = tid + j * 256;
        int lr  = idx >> 3;
        int c4  = idx & 7;
        int gr  = base + lr;
        if (gr > N_NODES - 1) gr = N_NODES - 1;           // clamp (stores guarded)
        const float* src = x + (size_t)gr * NF + kc * 32 + c4 * 4;
        unsigned int dst = xs_smem + (unsigned int)((lr * 32 + ((c4 ^ (lr & 7)) * 4)) * 4);
        cp16(dst, src);
    }
}

__device__ __forceinline__ void proj_compute_chunk(
    const unsigned int* __restrict__ xs, int kc, const uint2* __restrict__ w_p,
    float c[8][4], int warp, int qp, int qt, int lane) {
    int lr0 = warp * 16 + qp;
    int lr1 = lr0 + 8;
#pragma unroll
    for (int kl = 0; kl < 4; kl++) {
        int sw0 = (((2 * kl)     ^ qp) * 4) + qt;
        int sw1 = (((2 * kl + 1) ^ qp) * 4) + qt;
        unsigned int A0 = xs[lr0 * 32 + sw0];
        unsigned int A2 = xs[lr0 * 32 + sw1];
        unsigned int A1 = xs[lr1 * 32 + sw0];
        unsigned int A3 = xs[lr1 * 32 + sw1];
        const uint2* wk = &w_p[(kc * 4 + kl) * 8 * 32 + lane];
#pragma unroll
        for (int nt = 0; nt < 8; nt++) {
            uint2 b = wk[nt * 32];
            asm volatile(
                "mma.sync.aligned.m16n8k8.row.col.f32.tf32.tf32.f32 "
                "{%0,%1,%2,%3},{%4,%5,%6,%7},{%8,%9},{%0,%1,%2,%3};"
                : "+f"(c[nt][0]), "+f"(c[nt][1]), "+f"(c[nt][2]), "+f"(c[nt][3])
                : "r"(A0), "r"(A1), "r"(A2), "r"(A3), "r"(b.x), "r"(b.y));
        }
    }
}

__global__ void __launch_bounds__(256)
k_proj_tc(const float* __restrict__ x, const float* __restrict__ xw,
          const float* __restrict__ W) {
    extern __shared__ unsigned int smem_u[];
    unsigned int* xs0 = smem_u;                       // buffer 0
    unsigned int* xs1 = smem_u + XS_WORDS;            // buffer 1
    uint2*        w_p = (uint2*)(smem_u + WP_OFF_W);
    float*        g_s = (float*)(smem_u + GS_OFF_W);

    int tid  = threadIdx.x;
    int lane = tid & 31;
    int warp = tid >> 5;
    int qp = lane >> 2, qt = lane & 3;
    int base = blockIdx.x * PROJ_ROWS;

    unsigned int xs0_sm, xs1_sm;
    {
        unsigned long long a0 = __cvta_generic_to_shared(xs0);
        unsigned long long a1 = __cvta_generic_to_shared(xs1);
        xs0_sm = (unsigned int)a0;
        xs1_sm = (unsigned int)a1;
    }

    // chunk 0 in flight immediately
    proj_load_chunk(xs0_sm, x, base, 0, tid);
    cp_commit();

    if (tid < NF) {
        float wv = xw[tid];
        g_s[tid] = (fabsf(wv) > 0.f) ? 1.f / (1.f + __expf(-wv)) : 0.f;
    }
    __syncthreads();
    for (int i = tid; i < 16 * 8 * 32; i += 256) {
        int li = i & 31;
        int nt = (i >> 5) & 7;
        int k  = i >> 8;
        int qpp = li >> 2, qtt = li & 3;
        int cls  = nt * 8 + qpp;
        int col0 = k * 8 + qtt;
        float b0 = W[cls * NF + col0]     * g_s[col0];
        float b1 = W[cls * NF + col0 + 4] * g_s[col0 + 4];
        w_p[(k * 8 + nt) * 32 + li] = make_uint2(f2tf32(b0), f2tf32(b1));
    }

    proj_load_chunk(xs1_sm, x, base, 1, tid);
    cp_commit();

    float c[8][4];
#pragma unroll
    for (int nt = 0; nt < 8; nt++) { c[nt][0]=0.f; c[nt][1]=0.f; c[nt][2]=0.f; c[nt][3]=0.f; }

    // kc=0 (buf0)
    cp_wait<1>();
    __syncthreads();                                   // also publishes w_p
    proj_compute_chunk(xs0, 0, w_p, c, warp, qp, qt, lane);
    __syncthreads();
    // kc=1 (buf1); prefetch chunk2 -> buf0
    proj_load_chunk(xs0_sm, x, base, 2, tid);
    cp_commit();
    cp_wait<1>();
    __syncthreads();
    proj_compute_chunk(xs1, 1, w_p, c, warp, qp, qt, lane);
    __syncthreads();
    // kc=2 (buf0); prefetch chunk3 -> buf1
    proj_load_chunk(xs1_sm, x, base, 3, tid);
    cp_commit();
    cp_wait<1>();
    __syncthreads();
    proj_compute_chunk(xs0, 2, w_p, c, warp, qp, qt, lane);
    // kc=3 (buf1)
    cp_wait<0>();
    __syncthreads();
    proj_compute_chunk(xs1, 3, w_p, c, warp, qp, qt, lane);

    int r0 = base + warp * 16 + qp;
    int r1 = r0 + 8;
    if (r0 < N_NODES) {
        float* z = g_z0 + (size_t)r0 * NC;
#pragma unroll
        for (int nt = 0; nt < 8; nt++)
            *(float2*)&z[nt * 8 + qt * 2] = make_float2(c[nt][0], c[nt][1]);
    }
    if (r1 < N_NODES) {
        float* z = g_z0 + (size_t)r1 * NC;
#pragma unroll
        for (int nt = 0; nt < 8; nt++)
            *(float2*)&z[nt * 8 + qt * 2] = make_float2(c[nt][2], c[nt][3]);
    }
}

// ---------------- hop 1: z0 -> z1 (also resets g_packed for next call) ----------------
__global__ void __launch_bounds__(256)
k_prop_a() {
    const float2* zi = (const float2*)g_z0;
    float2*       zo = (float2*)g_z1;
    int n    = (blockIdx.x * blockDim.x + threadIdx.x) >> 5;
    int lane = threadIdx.x & 31;
    if (n >= N_NODES) return;
    if (lane == 0) g_packed[n] = 0ULL;
    int beg = g_indptr[n];
    int end = g_indptr[n + 1];
    float dv = g_dinv[n];
    float2 self = zi[(size_t)n * 32 + lane];
    float sw = dv * dv;
    float2 acc = make_float2(self.x * sw, self.y * sw);
    int e = beg;
    for (; e + 4 <= end; e += 4) {
        int2 ed0 = g_edge[e];
        int2 ed1 = g_edge[e + 1];
        int2 ed2 = g_edge[e + 2];
        int2 ed3 = g_edge[e + 3];
        float2 v0 = zi[(size_t)ed0.x * 32 + lane];
        float2 v1 = zi[(size_t)ed1.x * 32 + lane];
        float2 v2 = zi[(size_t)ed2.x * 32 + lane];
        float2 v3 = zi[(size_t)ed3.x * 32 + lane];
        float w0 = __int_as_float(ed0.y);
        float w1 = __int_as_float(ed1.y);
        float w2 = __int_as_float(ed2.y);
        float w3 = __int_as_float(ed3.y);
        acc.x += w0 * v0.x; acc.y += w0 * v0.y;
        acc.x += w1 * v1.x; acc.y += w1 * v1.y;
        acc.x += w2 * v2.x; acc.y += w2 * v2.y;
        acc.x += w3 * v3.x; acc.y += w3 * v3.y;
    }
    for (; e < end; e++) {
        int2 ed = g_edge[e];
        float w = __int_as_float(ed.y);
        float2 v = zi[(size_t)ed.x * 32 + lane];
        acc.x += w * v.x; acc.y += w * v.y;
    }
    zo[(size_t)n * 32 + lane] = acc;
}

// ---------------- hop 2 + bias + log_softmax fused ----------------
__global__ void __launch_bounds__(256)
k_prop_b(const float* __restrict__ bias, float* __restrict__ out) {
    const float2* zi = (const float2*)g_z1;
    int n    = (blockIdx.x * blockDim.x + threadIdx.x) >> 5;
    int lane = threadIdx.x & 31;
    if (n >= N_NODES) return;
    int beg = g_indptr[n];
    int end = g_indptr[n + 1];
    float dv = g_dinv[n];
    float2 self = zi[(size_t)n * 32 + lane];
    float sw = dv * dv;
    float2 acc = make_float2(self.x * sw, self.y * sw);
    int e = beg;
    for (; e + 4 <= end; e += 4) {
        int2 ed0 = g_edge[e];
        int2 ed1 = g_edge[e + 1];
        int2 ed2 = g_edge[e + 2];
        int2 ed3 = g_edge[e + 3];
        float2 v0 = zi[(size_t)ed0.x * 32 + lane];
        float2 v1 = zi[(size_t)ed1.x * 32 + lane];
        float2 v2 = zi[(size_t)ed2.x * 32 + lane];
        float2 v3 = zi[(size_t)ed3.x * 32 + lane];
        float w0 = __int_as_float(ed0.y);
        float w1 = __int_as_float(ed1.y);
        float w2 = __int_as_float(ed2.y);
        float w3 = __int_as_float(ed3.y);
        acc.x += w0 * v0.x; acc.y += w0 * v0.y;
        acc.x += w1 * v1.x; acc.y += w1 * v1.y;
        acc.x += w2 * v2.x; acc.y += w2 * v2.y;
        acc.x += w3 * v3.x; acc.y += w3 * v3.y;
    }
    for (; e < end; e++) {
        int2 ed = g_edge[e];
        float w = __int_as_float(ed.y);
        float2 v = zi[(size_t)ed.x * 32 + lane];
        acc.x += w * v.x; acc.y += w * v.y;
    }
    float2 bv = ((const float2*)bias)[lane];
    float v0 = acc.x + bv.x;
    float v1 = acc.y + bv.y;
    float m = fmaxf(v0, v1);
#pragma unroll
    for (int off = 16; off >= 1; off >>= 1)
        m = fmaxf(m, __shfl_xor_sync(0xffffffffu, m, off));
    float s = __expf(v0 - m) + __expf(v1 - m);
#pragma unroll
    for (int off = 16; off >= 1; off >>= 1)
        s += __shfl_xor_sync(0xffffffffu, s, off);
    float lse = m + __logf(s);
    ((float2*)out)[(size_t)n * 32 + lane] = make_float2(v0 - lse, v1 - lse);
}

// ---------------- launch (6 kernels, single stream) ----------------
extern "C" void kernel_launch(void* const* d_in, const int* in_sizes, int n_in,
                              void* d_out, int out_size) {
    const float* x   = (const float*)d_in[0];
    const int*   ei  = (const int*)d_in[1];     // int32 (JAX x64 disabled)
    const float* ewt = (const float*)d_in[2];
    const float* xw  = (const float*)d_in[3];
    const float* lw  = (const float*)d_in[4];
    const float* lb  = (const float*)d_in[5];
    float*       out = (float*)d_out;
    const int*   ei_row = ei;
    const int*   ei_col = ei + N_EDGES;

    cudaFuncSetAttribute(k_proj_tc, cudaFuncAttributeMaxDynamicSharedMemorySize,
                         PROJ_SMEM_B);

    const int T = 256;
    k_edge_prep<<<(N_EDGES + T - 1) / T, T>>>(ei_col, ewt);
    k_scan<<<SCAN_B, SCAN_T>>>();
    k_csr_fill<<<(N_EDGES + T - 1) / T, T>>>(ei_row, ei_col, ewt);

    k_proj_tc<<<PROJ_BLOCKS, T, PROJ_SMEM_B>>>(x, xw, lw);

    int prop_blocks = (N_NODES * 32 + T - 1) / T;
    k_prop_a<<<prop_blocks, T>>>();
    k_prop_b<<<prop_blocks, T>>>(lb, out);
}